// round 17
// baseline (speedup 1.0000x reference)
#include <cuda_runtime.h>
#include <cuda_fp16.h>
#include <math.h>
#include <stdint.h>

#define NB 16
#define NC 256
#define NH 64
#define NW 64
#define NTAP 9
#define SEXP (NC*NC*NTAP)
#define QP 66
#define QN (QP*QP)                  /* 4356 padded pixels */
#define TILE_M 128
#define TILE_N 144
#define KC 16
#define NCHUNK 16
#define NTHREADS 192
#define A_TAP_BYTES 4096            /* 128 rows x 16 ch fp16, fragment-major */
#define A_CHUNK_BYTES (NTAP*A_TAP_BYTES)   /* 36864 */
#define B_PITCH 32                  /* 32B data per pixel row (16 ch fp16) */
#define B_ROWS 280                  /* 144 + 2*67 = 278, padded */
#define B_BYTES (B_ROWS*B_PITCH)    /* 8960 */
#define SMEM_TOTAL (2*A_CHUNK_BYTES + 2*B_BYTES)  /* 91648 -> 2 CTAs/SM */
#define QTILES 31                   /* 31*144 = 4464 >= 4356 */
#define NTILES (NB*2*QTILES)        /* 992 */
#define GRIDX 296                   /* persistent: 2 CTAs per SM */
#define FOLD_BLOCKS (SEXP/256)      /* 2304 */
#define XPAD_BLOCKS (4*QP*NB)       /* 4224 */

__device__ float g_pooled[NB*NC];   // zero at module load; conv re-zeroes at end
__device__ float g_routing[NB*4];
// A fp16 fragment-major: [b][otile(2)][chunk(16)][t(9)][inner 2048 halves]
// inner = (mblk*32 + lane)*8 + reg*2 + e   (m16n8k16 A fragment, reg=khi*2+ohi)
__device__ __align__(1024) __half g_weff[(size_t)NB*NTAP*NC*NC];
// B fp16: [b][q][c_perm], perm within 16-group: pos16 = tig*4 + khi*2 + e
__device__ __align__(1024) __half g_xpad[(size_t)NB*QN*NC];

// ------------------------------------------------------------------ helpers
__device__ __forceinline__ uint32_t s2u(const void* p){
    uint32_t a;
    asm("{ .reg .u64 t; cvta.to.shared.u64 t, %1; cvt.u32.u64 %0, t; }" : "=r"(a) : "l"(p));
    return a;
}
__device__ __forceinline__ void cp16(uint32_t dst, const void* src, int szbytes){
    asm volatile("cp.async.cg.shared.global [%0], [%1], 16, %2;"
                 :: "r"(dst), "l"(src), "r"(szbytes) : "memory");
}
__device__ __forceinline__ void cp_commit(){
    asm volatile("cp.async.commit_group;" ::: "memory");
}
template<int N> __device__ __forceinline__ void cp_wait(){
    asm volatile("cp.async.wait_group %0;" :: "n"(N) : "memory");
}
__device__ __forceinline__ void mma16(float* d, const uint4 a, const uint32_t b0,
                                      const uint32_t b1){
    asm volatile("mma.sync.aligned.m16n8k16.row.col.f32.f16.f16.f32 "
        "{%0,%1,%2,%3}, {%4,%5,%6,%7}, {%8,%9}, {%0,%1,%2,%3};"
        : "+f"(d[0]), "+f"(d[1]), "+f"(d[2]), "+f"(d[3])
        : "r"(a.x), "r"(a.y), "r"(a.z), "r"(a.w), "r"(b0), "r"(b1));
}

// ------------------------------------------------------------------ prep
// Fused xpad + global-average-pool: reads x once. Pool accumulates into
// g_pooled via atomics (conv zeroes it at kernel end for the next replay).
__global__ void xpad_pool_kernel(const float* __restrict__ x) {
    __shared__ float s[64*65];
    int blk = blockIdx.x;
    int c0 = (blk & 3) * 64;
    int hp = (blk >> 2) % QP;
    int b  = blk / (4*QP);
    int h = hp - 1;
    bool hv = (h >= 0 && h < NH);
    if (hv) {
        const float* xp = x + ((size_t)(b*NC + c0))*(NH*NW) + (size_t)h*NW;
        for (int j = 0; j < 16; ++j) {
            int idx = j*256 + threadIdx.x;
            int i = idx >> 6, w = idx & 63;
            s[w*65 + i] = xp[(size_t)i*(NH*NW) + w];
        }
    }
    __syncthreads();
    if (hv && threadIdx.x < 64) {
        int i = threadIdx.x;
        float sum = 0.f;
        #pragma unroll 8
        for (int w = 0; w < 64; ++w) sum += s[w*65 + i];
        atomicAdd(&g_pooled[b*NC + c0 + i], sum * (1.0f/(NH*NW)));
    }
    __half* op = g_xpad + ((size_t)b*QN + (size_t)hp*QP)*NC + c0;
    for (int j = 0; j < 17; ++j) {
        int idx = j*256 + threadIdx.x;
        if (idx >= QP*64) break;
        int i = idx & 63, wp = idx >> 6;
        float v = 0.f;
        if (hv && wp >= 1 && wp <= 64) v = s[(wp-1)*65 + i];
        // perm within 16-group: pos16 = tig*4 + khi*2 + e
        int k = i & 15;
        int e = k & 1, tg = (k >> 1) & 3, khi = (k >> 3) & 1;
        int ipos = (i & ~15) | (tg*4 + khi*2 + e);
        op[(size_t)wp*NC + ipos] = __float2half_rn(v);
    }
}

__global__ void route_kernel(const float* __restrict__ wr, const float* __restrict__ br) {
    int t = threadIdx.x;
    if (t >= NB*4) return;
    int b = t >> 2, e = t & 3;
    float acc = br[e];
    const float* pw = wr + e*NC;
    const float* pp = g_pooled + b*NC;
    #pragma unroll 8
    for (int c = 0; c < NC; ++c) acc = fmaf(pp[c], pw[c], acc);
    g_routing[t] = 1.f/(1.f + __expf(-acc));
}

// Destination-coalesced fold into [otile][chunk(16)][t][inner 2048] layout.
__global__ void fold_kernel(const float* __restrict__ we) {
    int lin = blockIdx.x * 256 + threadIdx.x;   // 0 .. 589823
    int inner = lin & 2047;
    int rest  = lin >> 11;          // 0..287
    int t     = rest % 9;
    int oc    = rest / 9;           // 0..31
    int chunk = oc & 15;
    int otile = oc >> 4;
    int e    = inner & 1;
    int reg  = (inner >> 1) & 3;
    int lane = (inner >> 3) & 31;
    int mblk = (inner >> 8) & 7;
    int tig = lane & 3, g8 = lane >> 2;
    int khi = reg >> 1, ohi = reg & 1;
    int o = otile*128 + mblk*16 + ohi*8 + g8;
    int c = chunk*16 + khi*8 + tig*2 + e;

    size_t wi = ((size_t)o*NC + c)*NTAP + t;
    float w0 = we[wi], w1 = we[wi + (size_t)SEXP];
    float w2 = we[wi + 2*(size_t)SEXP], w3 = we[wi + 3*(size_t)SEXP];
    #pragma unroll
    for (int b = 0; b < NB; ++b) {
        const float* r = g_routing + b*4;
        g_weff[(size_t)b*(NTAP*NC*NC) + lin] =
            __float2half_rn(w0*r[0] + w1*r[1] + w2*r[2] + w3*r[3]);
    }
}

// ------------------------------------------------------------------ conv GEMM
// per-CTA smem: [A buf0 36KB][A buf1 36KB][B buf0 8.75KB][B buf1 8.75KB]
__device__ __forceinline__ void decode_tile(int tau, int& b, int& otile, int& q0){
    b = tau / (2*QTILES);
    int r = tau - b*(2*QTILES);
    otile = r / QTILES;
    q0 = (r - otile*QTILES) * TILE_N;
}

__device__ __forceinline__ void load_chunk(uint32_t sb, int bufsel, int chunk,
                                           int b, int otile, int q0, int tid)
{
    const __half* aG = g_weff + (size_t)b*(NTAP*NC*NC)
                     + ((size_t)(otile*16 + chunk)*9)*2048;
    uint32_t aDst = sb + bufsel*A_CHUNK_BYTES;
    #pragma unroll
    for (int j = 0; j < 12; ++j) {
        int seg = tid + j*NTHREADS;
        cp16(aDst + seg*16, aG + (size_t)seg*8, 16);
    }
    const __half* bC = g_xpad + (size_t)b*QN*NC + chunk*KC;
    uint32_t bDst = sb + 2*A_CHUNK_BYTES + bufsel*B_BYTES;
    #pragma unroll
    for (int jj = 0; jj < 3; ++jj) {
        int seg = tid + jj*NTHREADS;
        if (seg < 278*2) {
            int row = seg >> 1, j = seg & 1;
            int q = q0 - 67 + row;
            bool v = ((unsigned)q < (unsigned)QN);
            const __half* src = bC + (size_t)(v ? q : 0)*NC + j*8;
            cp16(bDst + row*B_PITCH + j*16, src, v ? 16 : 0);
        }
    }
}

__global__ void __launch_bounds__(NTHREADS, 2)
conv_mma_kernel(const float* __restrict__ gamma, const float* __restrict__ beta,
                const float* __restrict__ mean,  const float* __restrict__ var,
                float* __restrict__ out)
{
    extern __shared__ __align__(128) char smem[];
    const uint32_t sb = s2u(smem);
    const int tid = threadIdx.x, wid = tid >> 5, lid = tid & 31;
    const int wmM = wid & 1;          // 2 warps over M (64 rows each)
    const int wnN = wid >> 1;         // 3 warps over N (48 px each)
    const int g = lid >> 2, tig = lid & 3;

    int tau = blockIdx.x;
    if (tau < NTILES) {
        int cb, cot, cq0;
        decode_tile(tau, cb, cot, cq0);
        int nb = cb, not2 = cot, nq0 = cq0;

        float acc[4][6][4];
        #pragma unroll
        for (int mi = 0; mi < 4; ++mi)
            #pragma unroll
            for (int ni = 0; ni < 6; ++ni)
                #pragma unroll
                for (int k = 0; k < 4; ++k) acc[mi][ni][k] = 0.f;

        load_chunk(sb, 0, 0, cb, cot, cq0, tid);
        cp_commit();
        int cnt = 0;

        #pragma unroll 1
        while (tau < NTILES) {
            #pragma unroll 1
            for (int chunk = 0; chunk < NCHUNK; ++chunk) {
                __syncthreads();
                if (chunk + 1 < NCHUNK) {
                    load_chunk(sb, (cnt+1) & 1, chunk + 1, cb, cot, cq0, tid);
                } else if (tau + GRIDX < NTILES) {
                    decode_tile(tau + GRIDX, nb, not2, nq0);
                    load_chunk(sb, (cnt+1) & 1, 0, nb, not2, nq0, tid);
                }
                cp_commit();
                cp_wait<1>();
                __syncthreads();

                const char* aBuf = smem + (cnt & 1)*A_CHUNK_BYTES;
                const char* bBase = smem + 2*A_CHUNK_BYTES + (cnt & 1)*B_BYTES;
                const char* bLane = bBase + (wnN*48 + g + 67)*B_PITCH + tig*8;

                #pragma unroll
                for (int t = 0; t < NTAP; ++t) {
                    const int dh = t / 3, dw = t - dh*3;
                    const char* aT = aBuf + t*A_TAP_BYTES;
                    const char* bW = bLane + ((dh-1)*QP + (dw-1))*B_PITCH;
                    uint2 bf[6];
                    #pragma unroll
                    for (int ni = 0; ni < 6; ++ni)
                        bf[ni] = *(const uint2*)(bW + ni*8*B_PITCH);
                    uint4 a[4];
                    #pragma unroll
                    for (int mi = 0; mi < 4; ++mi)
                        a[mi] = *(const uint4*)(aT + ((wmM*4 + mi)*32 + lid)*16);
                    #pragma unroll
                    for (int mi = 0; mi < 4; ++mi)
                        #pragma unroll
                        for (int ni = 0; ni < 6; ++ni)
                            mma16(acc[mi][ni], a[mi], bf[ni].x, bf[ni].y);
                }
                cnt++;
            }

            // ---------------- epilogue (next tile's chunk0 already in flight)
            {
                const int o0 = cot * TILE_M;
                float inv[4][2], add[4][2];
                #pragma unroll
                for (int mi = 0; mi < 4; ++mi)
                    #pragma unroll
                    for (int hi = 0; hi < 2; ++hi) {
                        int o = o0 + wmM*64 + mi*16 + g + hi*8;
                        float iv = gamma[o] * rsqrtf(var[o] + 1e-5f);
                        inv[mi][hi] = iv;
                        add[mi][hi] = beta[o] - mean[o] * iv;
                    }
                #pragma unroll
                for (int mi = 0; mi < 4; ++mi) {
                    #pragma unroll
                    for (int ni = 0; ni < 6; ++ni) {
                        #pragma unroll
                        for (int k = 0; k < 4; ++k) {
                            int hi = k >> 1, c = k & 1;
                            int q = cq0 + wnN*48 + ni*8 + 2*tig + c;
                            int hp = q / QP, wp = q - hp*QP;
                            if (q < QN && hp >= 1 && hp <= NH && wp >= 1 && wp <= NW) {
                                int o = o0 + wmM*64 + mi*16 + g + hi*8;
                                float z = acc[mi][ni][k] * inv[mi][hi] + add[mi][hi];
                                out[(((size_t)cb*NC + o)*NH + hp - 1)*NW + wp - 1] =
                                    z / (1.f + __expf(-z));
                            }
                            acc[mi][ni][k] = 0.f;
                        }
                    }
                }
            }
            tau += GRIDX;
            cb = nb; cot = not2; cq0 = nq0;
        }
    }

    // reset pooled accumulator for the next graph replay (after route used it)
    if (blockIdx.x == 0) {
        for (int i = tid; i < NB*NC; i += NTHREADS) g_pooled[i] = 0.f;
    }
}

// ------------------------------------------------------------------ launch
extern "C" void kernel_launch(void* const* d_in, const int* in_sizes, int n_in,
                              void* d_out, int out_size) {
    const float* x        = (const float*)d_in[0];
    const float* w_route  = (const float*)d_in[1];
    const float* b_route  = (const float*)d_in[2];
    const float* w_expert = (const float*)d_in[3];
    const float* bn_gamma = (const float*)d_in[4];
    const float* bn_beta  = (const float*)d_in[5];
    const float* bn_mean  = (const float*)d_in[6];
    const float* bn_var   = (const float*)d_in[7];
    float* out = (float*)d_out;

    cudaFuncSetAttribute(conv_mma_kernel,
                         cudaFuncAttributeMaxDynamicSharedMemorySize, SMEM_TOTAL);

    xpad_pool_kernel<<<XPAD_BLOCKS, 256>>>(x);
    route_kernel<<<1, 64>>>(w_route, b_route);
    fold_kernel<<<FOLD_BLOCKS, 256>>>(w_expert);
    conv_mma_kernel<<<GRIDX, NTHREADS, SMEM_TOTAL>>>(bn_gamma, bn_beta, bn_mean, bn_var, out);
}